// round 7
// baseline (speedup 1.0000x reference)
#include <cuda_runtime.h>
#include <math.h>
#include <stdint.h>

#define BB 4
#define CC 64
#define HH 128
#define WW 128
#define OO 64
#define KK 3
#define K2 9

// ---------------- scratch (device globals; no allocation allowed) ------------
__device__ float g_xT[BB*HH*WW*CC];     // x transposed to (B,H,W,C)   ~16.8MB
__device__ float g_off[BB*HH*WW*18];    // per-pixel packed offsets (9 y, 9 x)
__device__ float g_mm [BB*HH*WW];       // per-pixel modulation mean
__device__ float g_wbh[K2*CC*OO];       // per-tap weight hi, [k][c][o]
__device__ float g_wbl[K2*CC*OO];       // per-tap weight lo, [k][c][o]

__device__ __forceinline__ uint32_t tf32_bits(float v) {
    uint32_t u;
    asm("cvt.rna.tf32.f32 %0, %1;" : "=r"(u) : "f"(v));
    return u;
}
__device__ __forceinline__ void mma_tf32(float* d, const uint32_t* a,
                                         uint32_t b0, uint32_t b1) {
    asm volatile(
        "mma.sync.aligned.m16n8k8.row.col.f32.tf32.tf32.f32 "
        "{%0,%1,%2,%3}, {%4,%5,%6,%7}, {%8,%9}, {%0,%1,%2,%3};"
        : "+f"(d[0]), "+f"(d[1]), "+f"(d[2]), "+f"(d[3])
        : "r"(a[0]), "r"(a[1]), "r"(a[2]), "r"(a[3]), "r"(b0), "r"(b1));
}

// ---------------- kernel 0: NCHW -> NHWC transpose ---------------------------
__global__ void k_transpose(const float* __restrict__ x) {
    int b = blockIdx.x >> 7;
    int h = blockIdx.x & 127;
    __shared__ float tile[CC][WW + 1];
    for (int idx = threadIdx.x; idx < CC * WW; idx += blockDim.x) {
        int c = idx >> 7, w = idx & 127;
        tile[c][w] = x[((b * CC + c) * HH + h) * WW + w];
    }
    __syncthreads();
    for (int idx = threadIdx.x; idx < CC * WW; idx += blockDim.x) {
        int w = idx >> 6, c = idx & 63;
        g_xT[((b * HH + h) * WW + w) * CC + c] = tile[c][w];
    }
}

// -------- kernel 1: weight -> per-tap hi/lo [k][c][o] ------------------------
__global__ void k_wreorg(const float* __restrict__ weight) {
    for (int idx = blockIdx.x * blockDim.x + threadIdx.x; idx < K2 * CC * OO;
         idx += gridDim.x * blockDim.x) {
        int k = idx >> 12;
        int r = idx & 4095;
        int c = r >> 6;
        int o = r & 63;
        float w = weight[(o * CC + c) * K2 + k];
        uint32_t hb = tf32_bits(w);
        float hi = __uint_as_float(hb);
        g_wbh[idx] = hi;
        g_wbl[idx] = __uint_as_float(tf32_bits(w - hi));
    }
}

// ---------------- kernel 2: fused offset(18) + mod(9) 3x3 conv ---------------
#define XROWS 4
#define XPX   130
#define CHP   17
#define XS_FLOATS (XROWS * XPX * CHP)
#define WS_FLOATS (K2 * 16 * 28)
#define SMEM_OFFMOD ((XS_FLOATS + WS_FLOATS) * 4)

#define ACC27(v, wp) do {                                                      \
    const float4* w4_ = reinterpret_cast<const float4*>(wp);                   \
    float4 q_;                                                                 \
    q_ = w4_[0]; acc[0]+=(v)*q_.x; acc[1]+=(v)*q_.y; acc[2]+=(v)*q_.z; acc[3]+=(v)*q_.w; \
    q_ = w4_[1]; acc[4]+=(v)*q_.x; acc[5]+=(v)*q_.y; acc[6]+=(v)*q_.z; acc[7]+=(v)*q_.w; \
    q_ = w4_[2]; acc[8]+=(v)*q_.x; acc[9]+=(v)*q_.y; acc[10]+=(v)*q_.z; acc[11]+=(v)*q_.w; \
    q_ = w4_[3]; acc[12]+=(v)*q_.x; acc[13]+=(v)*q_.y; acc[14]+=(v)*q_.z; acc[15]+=(v)*q_.w; \
    q_ = w4_[4]; acc[16]+=(v)*q_.x; acc[17]+=(v)*q_.y; acc[18]+=(v)*q_.z; acc[19]+=(v)*q_.w; \
    q_ = w4_[5]; acc[20]+=(v)*q_.x; acc[21]+=(v)*q_.y; acc[22]+=(v)*q_.z; acc[23]+=(v)*q_.w; \
    q_ = w4_[6]; acc[24]+=(v)*q_.x; acc[25]+=(v)*q_.y; acc[26]+=(v)*q_.z;     \
} while (0)

__global__ void __launch_bounds__(256, 2) k_offmod(const float* __restrict__ offset_w,
                                                   const float* __restrict__ offset_b,
                                                   const float* __restrict__ mod_w,
                                                   const float* __restrict__ mod_b) {
    extern __shared__ __align__(16) float dynsm[];
    float* xs = dynsm;
    float* ws = dynsm + XS_FLOATS;

    int b  = blockIdx.y;
    int r0 = blockIdx.x * 2;
    int tid = threadIdx.x;
    int p = tid & 127;
    int r = tid >> 7;

    float acc[27];
#pragma unroll
    for (int j = 0; j < 27; j++) acc[j] = 0.f;

    for (int chunk = 0; chunk < 4; chunk++) {
        int ch0 = chunk * 16;
        __syncthreads();

        for (int i = tid; i < WS_FLOATS; i += 256) {
            int t   = i / 448;
            int rem = i % 448;
            int c   = rem / 28;
            int ch  = rem % 28;
            float wv = 0.f;
            if (ch < 18)      wv = offset_w[(ch * CC + ch0 + c) * K2 + t];
            else if (ch < 27) wv = mod_w[((ch - 18) * CC + ch0 + c) * K2 + t];
            ws[i] = wv;
        }

        for (int i = tid; i < XROWS * XPX * 4; i += 256) {
            int c4  = i & 3;
            int rem = i >> 2;
            int px  = rem % XPX;
            int row = rem / XPX;
            int y = r0 - 1 + row;
            int x = px - 1;
            float4 v = make_float4(0.f, 0.f, 0.f, 0.f);
            if (y >= 0 && y < HH && x >= 0 && x < WW)
                v = *reinterpret_cast<const float4*>(
                    &g_xT[((size_t)(b * HH + y) * WW + x) * CC + ch0 + c4 * 4]);
            float* d = &xs[(row * XPX + px) * CHP + c4 * 4];
            d[0] = v.x; d[1] = v.y; d[2] = v.z; d[3] = v.w;
        }
        __syncthreads();

#pragma unroll
        for (int t = 0; t < K2; t++) {
            int ty = t / 3, tx = t % 3;
            const float* xrow = &xs[((r + ty) * XPX + (p + tx)) * CHP];
            const float* wsb  = &ws[t * 16 * 28];
#pragma unroll
            for (int c = 0; c < 16; c++) {
                float v = xrow[c];
                ACC27(v, &wsb[c * 28]);
            }
        }
    }

    int pix = (b * HH + r0 + r) * WW + p;
    float* op = &g_off[(size_t)pix * 18];
#pragma unroll
    for (int j = 0; j < 18; j++) op[j] = acc[j] + offset_b[j];

    float mm = 0.f;
#pragma unroll
    for (int j = 0; j < 9; j++) {
        float z = acc[18 + j] + mod_b[j];
        mm += 1.f / (1.f + expf(-z));
    }
    g_mm[pix] = mm * (1.f / 9.f);
}

// -------- kernel 3: gather + warp-level tf32 mma.sync GEMM -------------------
// Block = one row (128 px) x 64 outputs, 8 warps; warp w = pixels 16w..16w+15.
// ss[pix][c] stride 72 (A-frag LDS bank = 8g+tg: conflict-free).
// wk[c][o]  stride 72 (B-frag LDS bank = 8tg+g: conflict-free).
// D accumulates in registers across 9 taps; 3xTF32 for fp32-grade accuracy.
#define SS_STR 72
#define WK_STR 72
#define WKH_OFF 0
#define WKL_OFF (CC * WK_STR)              // 4608
#define SS_OFF  (2 * CC * WK_STR)          // 9216
#define BS_OFF  (SS_OFF + HH * SS_STR)     // 18432  (HH=128 px rows)
#define SMEM_MAIN ((BS_OFF + 64) * 4)      // 73984 B
#define OUT_STR 130

__global__ void __launch_bounds__(256) k_main(const float* __restrict__ bias,
                                              float* __restrict__ out) {
    extern __shared__ __align__(16) float dyn[];
    float* wkh = dyn + WKH_OFF;
    float* wkl = dyn + WKL_OFF;
    float* ss  = dyn + SS_OFF;
    float* bs  = dyn + BS_OFF;

    int h = blockIdx.x;
    int b = blockIdx.y;
    int tid  = threadIdx.x;
    int warp = tid >> 5;
    int lane = tid & 31;
    int g  = lane >> 2;      // group id 0..7
    int tg = lane & 3;       // thread-in-group 0..3

    if (tid < OO) bs[tid] = bias[tid];

    // gather mapping: warp = 2 pixels x 16 lanes; lane owns 4 channels
    int hw = lane >> 4;
    int f4 = lane & 15;

    // mma mapping: warp owns pixels px0..px0+15
    int px0 = warp * 16;

    float d[8][4];
#pragma unroll
    for (int j = 0; j < 8; j++)
#pragma unroll
        for (int i = 0; i < 4; i++) d[j][i] = 0.f;

    for (int k = 0; k < K2; k++) {
        if (k) __syncthreads();            // previous tap's LDS reads done

        // ---- stage weight hi/lo [c][o] at stride 72 ----
        {
            const float4* sh = reinterpret_cast<const float4*>(&g_wbh[k << 12]);
            const float4* sl = reinterpret_cast<const float4*>(&g_wbl[k << 12]);
#pragma unroll
            for (int i = 0; i < 4; i++) {
                int idx = tid + i * 256;   // 1024 float4s
                int c  = idx >> 4;
                int o4 = idx & 15;
                reinterpret_cast<float4*>(&wkh[c * WK_STR])[o4] = sh[idx];
                reinterpret_cast<float4*>(&wkl[c * WK_STR])[o4] = sl[idx];
            }
        }

        // ---- gather: 8 passes, 2 pixels per warp per pass ----
        int ky = k / 3 - 1, kx = k % 3 - 1;
#pragma unroll
        for (int pass = 0; pass < 8; pass++) {
            int pix = pass * 16 + warp * 2 + hw;
            const float* offp = &g_off[(size_t)((b * HH + h) * WW + pix) * 18];
            float sy = (float)(h + ky) + offp[k];
            float sx = (float)(pix + kx) + offp[9 + k];
            float fy0 = floorf(sy), fx0 = floorf(sx);
            int iy0 = (int)fy0, ix0 = (int)fx0;
            float ay = sy - fy0, ax = sx - fx0;
            float wy[2] = {1.f - ay, ay};
            float wx[2] = {1.f - ax, ax};

            float v0 = 0.f, v1 = 0.f, v2 = 0.f, v3 = 0.f;
#pragma unroll
            for (int q = 0; q < 4; q++) {
                int iy = iy0 + (q >> 1), ix = ix0 + (q & 1);
                bool ok = (iy >= 0 && iy < HH && ix >= 0 && ix < WW);
                float wt = ok ? wy[q >> 1] * wx[q & 1] : 0.f;
                int iyc = min(max(iy, 0), HH - 1);
                int ixc = min(max(ix, 0), WW - 1);
                float4 a = reinterpret_cast<const float4*>(
                    &g_xT[((size_t)(b * HH + iyc) * WW + ixc) * CC])[f4];
                v0 = fmaf(wt, a.x, v0);
                v1 = fmaf(wt, a.y, v1);
                v2 = fmaf(wt, a.z, v2);
                v3 = fmaf(wt, a.w, v3);
            }
            float4 res = make_float4(v0, v1, v2, v3);
            *reinterpret_cast<float4*>(&ss[pix * SS_STR + f4 * 4]) = res;
        }

        __syncthreads();

        // ---- mma: 8 k-steps x 8 n-tiles x 3 passes -----------------------
        const float* arow0 = &ss[(px0 + g) * SS_STR];        // rows g / g+8
        const float* arow1 = arow0 + 8 * SS_STR;
#pragma unroll
        for (int s = 0; s < 8; s++) {
            int kk = s * 8 + tg;
            float v0 = arow0[kk];
            float v1 = arow1[kk];
            float v2 = arow0[kk + 4];
            float v3 = arow1[kk + 4];
            uint32_t ah[4], al[4];
            ah[0] = tf32_bits(v0); al[0] = tf32_bits(v0 - __uint_as_float(ah[0]));
            ah[1] = tf32_bits(v1); al[1] = tf32_bits(v1 - __uint_as_float(ah[1]));
            ah[2] = tf32_bits(v2); al[2] = tf32_bits(v2 - __uint_as_float(ah[2]));
            ah[3] = tf32_bits(v3); al[3] = tf32_bits(v3 - __uint_as_float(ah[3]));

            const float* bh0 = &wkh[(s * 8 + tg) * WK_STR + g];
            const float* bl0 = &wkl[(s * 8 + tg) * WK_STR + g];
#pragma unroll
            for (int j = 0; j < 8; j++) {
                uint32_t b0h = __float_as_uint(bh0[j * 8]);
                uint32_t b1h = __float_as_uint(bh0[4 * WK_STR + j * 8]);
                uint32_t b0l = __float_as_uint(bl0[j * 8]);
                uint32_t b1l = __float_as_uint(bl0[4 * WK_STR + j * 8]);
                mma_tf32(d[j], ah, b0h, b1h);
                mma_tf32(d[j], al, b0h, b1h);
                mma_tf32(d[j], ah, b0l, b1l);
            }
        }
    }

    // ---- epilogue: D -> smem transpose -> coalesced NCHW stores ----
    __syncthreads();
    float* outb = dyn;      // reuse wkh/wkl region: [64][OUT_STR]
#pragma unroll
    for (int j = 0; j < 8; j++) {
        int o = j * 8 + 2 * tg;
        outb[o * OUT_STR + px0 + g]           = d[j][0];
        outb[(o + 1) * OUT_STR + px0 + g]     = d[j][1];
        outb[o * OUT_STR + px0 + g + 8]       = d[j][2];
        outb[(o + 1) * OUT_STR + px0 + g + 8] = d[j][3];
    }
    __syncthreads();

    size_t mmbase = (size_t)(b * HH + h) * WW;
#pragma unroll
    for (int i = 0; i < 32; i++) {
        int idx = tid + i * 256;            // 8192 = 64 o x 128 px
        int o   = idx >> 7;
        int pix = idx & 127;
        float val = outb[o * OUT_STR + pix];
        out[((size_t)(b * OO + o) * HH + h) * WW + pix] =
            val * g_mm[mmbase + pix] + bs[o];
    }
}

// ---------------- launch -----------------------------------------------------
extern "C" void kernel_launch(void* const* d_in, const int* in_sizes, int n_in,
                              void* d_out, int out_size) {
    const float* x        = (const float*)d_in[0];
    const float* weight   = (const float*)d_in[1];
    const float* bias     = (const float*)d_in[2];
    const float* offset_w = (const float*)d_in[3];
    const float* offset_b = (const float*)d_in[4];
    const float* mod_w    = (const float*)d_in[5];
    const float* mod_b    = (const float*)d_in[6];
    float* out = (float*)d_out;

    cudaFuncSetAttribute(k_main, cudaFuncAttributeMaxDynamicSharedMemorySize,
                         SMEM_MAIN);
    cudaFuncSetAttribute(k_offmod, cudaFuncAttributeMaxDynamicSharedMemorySize,
                         SMEM_OFFMOD);

    k_transpose<<<BB * HH, 256>>>(x);
    k_wreorg<<<36, 256>>>(weight);
    k_offmod<<<dim3(HH / 2, BB), 256, SMEM_OFFMOD>>>(offset_w, offset_b,
                                                     mod_w, mod_b);
    k_main<<<dim3(HH, BB), 256, SMEM_MAIN>>>(bias, out);
}

// round 8
// speedup vs baseline: 1.7574x; 1.7574x over previous
#include <cuda_runtime.h>
#include <math.h>
#include <stdint.h>

#define BB 4
#define CC 64
#define HH 128
#define WW 128
#define OO 64
#define KK 3
#define K2 9

// ---------------- scratch (device globals; no allocation allowed) ------------
__device__ float  g_xT[BB*HH*WW*CC];     // x transposed to (B,H,W,C)
__device__ float  g_off[BB*HH*WW*18];    // per-pixel packed offsets (9 y, 9 x)
__device__ float  g_mm [BB*HH*WW];       // per-pixel modulation mean
__device__ float4 g_wf [K2*8*8*32];      // fragment-ready weights {b0h,b1h,b0l,b1l}

__device__ __forceinline__ uint32_t tf32_bits(float v) {
    uint32_t u;
    asm("cvt.rna.tf32.f32 %0, %1;" : "=r"(u) : "f"(v));
    return u;
}
__device__ __forceinline__ float tf32f(float v) {
    return __uint_as_float(tf32_bits(v));
}
__device__ __forceinline__ void mma_tf32(float* d, const uint32_t* a,
                                         float b0, float b1) {
    asm volatile(
        "mma.sync.aligned.m16n8k8.row.col.f32.tf32.tf32.f32 "
        "{%0,%1,%2,%3}, {%4,%5,%6,%7}, {%8,%9}, {%0,%1,%2,%3};"
        : "+f"(d[0]), "+f"(d[1]), "+f"(d[2]), "+f"(d[3])
        : "r"(a[0]), "r"(a[1]), "r"(a[2]), "r"(a[3]),
          "r"(__float_as_uint(b0)), "r"(__float_as_uint(b1)));
}

// ---------------- kernel 0: NCHW -> NHWC transpose ---------------------------
__global__ void k_transpose(const float* __restrict__ x) {
    int b = blockIdx.x >> 7;
    int h = blockIdx.x & 127;
    __shared__ float tile[CC][WW + 1];
    for (int idx = threadIdx.x; idx < CC * WW; idx += blockDim.x) {
        int c = idx >> 7, w = idx & 127;
        tile[c][w] = x[((b * CC + c) * HH + h) * WW + w];
    }
    __syncthreads();
    for (int idx = threadIdx.x; idx < CC * WW; idx += blockDim.x) {
        int w = idx >> 6, c = idx & 63;
        g_xT[((b * HH + h) * WW + w) * CC + c] = tile[c][w];
    }
}

// -------- kernel 1: weight -> fragment-ready hi/lo float4 image --------------
// g_wf[((k*8+s)*8+j)*32 + lane] = {Bh[s8+tg][j8+g], Bh[s8+tg+4][j8+g],
//                                  Bl[s8+tg][j8+g], Bl[s8+tg+4][j8+g]}
// where B[c][o] = weight[o][c][tap k], g = lane>>2, tg = lane&3.
__global__ void k_wreorg(const float* __restrict__ weight) {
    int idx = blockIdx.x * blockDim.x + threadIdx.x;
    if (idx >= K2 * 8 * 8 * 32) return;
    int lane = idx & 31;
    int j = (idx >> 5) & 7;
    int s = (idx >> 8) & 7;
    int k = idx >> 11;
    int o  = j * 8 + (lane >> 2);
    int c0 = s * 8 + (lane & 3);
    int c1 = c0 + 4;
    float w0 = weight[(o * CC + c0) * K2 + k];
    float w1 = weight[(o * CC + c1) * K2 + k];
    float h0 = tf32f(w0), l0 = tf32f(w0 - h0);
    float h1 = tf32f(w1), l1 = tf32f(w1 - h1);
    g_wf[idx] = make_float4(h0, h1, l0, l1);
}

// ---------------- kernel 2: fused offset(18) + mod(9) 3x3 conv ---------------
#define XROWS 4
#define XPX   130
#define CHP   17
#define XS_FLOATS (XROWS * XPX * CHP)
#define WS_FLOATS (K2 * 16 * 28)
#define SMEM_OFFMOD ((XS_FLOATS + WS_FLOATS) * 4)

#define ACC27(v, wp) do {                                                      \
    const float4* w4_ = reinterpret_cast<const float4*>(wp);                   \
    float4 q_;                                                                 \
    q_ = w4_[0]; acc[0]+=(v)*q_.x; acc[1]+=(v)*q_.y; acc[2]+=(v)*q_.z; acc[3]+=(v)*q_.w; \
    q_ = w4_[1]; acc[4]+=(v)*q_.x; acc[5]+=(v)*q_.y; acc[6]+=(v)*q_.z; acc[7]+=(v)*q_.w; \
    q_ = w4_[2]; acc[8]+=(v)*q_.x; acc[9]+=(v)*q_.y; acc[10]+=(v)*q_.z; acc[11]+=(v)*q_.w; \
    q_ = w4_[3]; acc[12]+=(v)*q_.x; acc[13]+=(v)*q_.y; acc[14]+=(v)*q_.z; acc[15]+=(v)*q_.w; \
    q_ = w4_[4]; acc[16]+=(v)*q_.x; acc[17]+=(v)*q_.y; acc[18]+=(v)*q_.z; acc[19]+=(v)*q_.w; \
    q_ = w4_[5]; acc[20]+=(v)*q_.x; acc[21]+=(v)*q_.y; acc[22]+=(v)*q_.z; acc[23]+=(v)*q_.w; \
    q_ = w4_[6]; acc[24]+=(v)*q_.x; acc[25]+=(v)*q_.y; acc[26]+=(v)*q_.z;     \
} while (0)

__global__ void __launch_bounds__(256, 2) k_offmod(const float* __restrict__ offset_w,
                                                   const float* __restrict__ offset_b,
                                                   const float* __restrict__ mod_w,
                                                   const float* __restrict__ mod_b) {
    extern __shared__ __align__(16) float dynsm[];
    float* xs = dynsm;
    float* ws = dynsm + XS_FLOATS;

    int b  = blockIdx.y;
    int r0 = blockIdx.x * 2;
    int tid = threadIdx.x;
    int p = tid & 127;
    int r = tid >> 7;

    float acc[27];
#pragma unroll
    for (int j = 0; j < 27; j++) acc[j] = 0.f;

    for (int chunk = 0; chunk < 4; chunk++) {
        int ch0 = chunk * 16;
        __syncthreads();

        for (int i = tid; i < WS_FLOATS; i += 256) {
            int t   = i / 448;
            int rem = i % 448;
            int c   = rem / 28;
            int ch  = rem % 28;
            float wv = 0.f;
            if (ch < 18)      wv = offset_w[(ch * CC + ch0 + c) * K2 + t];
            else if (ch < 27) wv = mod_w[((ch - 18) * CC + ch0 + c) * K2 + t];
            ws[i] = wv;
        }

        for (int i = tid; i < XROWS * XPX * 4; i += 256) {
            int c4  = i & 3;
            int rem = i >> 2;
            int px  = rem % XPX;
            int row = rem / XPX;
            int y = r0 - 1 + row;
            int x = px - 1;
            float4 v = make_float4(0.f, 0.f, 0.f, 0.f);
            if (y >= 0 && y < HH && x >= 0 && x < WW)
                v = *reinterpret_cast<const float4*>(
                    &g_xT[((size_t)(b * HH + y) * WW + x) * CC + ch0 + c4 * 4]);
            float* d = &xs[(row * XPX + px) * CHP + c4 * 4];
            d[0] = v.x; d[1] = v.y; d[2] = v.z; d[3] = v.w;
        }
        __syncthreads();

#pragma unroll
        for (int t = 0; t < K2; t++) {
            int ty = t / 3, tx = t % 3;
            const float* xrow = &xs[((r + ty) * XPX + (p + tx)) * CHP];
            const float* wsb  = &ws[t * 16 * 28];
#pragma unroll
            for (int c = 0; c < 16; c++) {
                float v = xrow[c];
                ACC27(v, &wsb[c * 28]);
            }
        }
    }

    int pix = (b * HH + r0 + r) * WW + p;
    float* op = &g_off[(size_t)pix * 18];
#pragma unroll
    for (int j = 0; j < 18; j++) op[j] = acc[j] + offset_b[j];

    float mm = 0.f;
#pragma unroll
    for (int j = 0; j < 9; j++) {
        float z = acc[18 + j] + mod_b[j];
        mm += 1.f / (1.f + expf(-z));
    }
    g_mm[pix] = mm * (1.f / 9.f);
}

// -------- kernel 3: warp-autonomous gather + tf32 mma pipeline ---------------
// Block = one row x 64 outputs, 8 warps. Warp w owns pixels 16w..16w+15 and is
// fully self-contained: per-warp double-buffered ss, B fragments via LDG.128
// from the fragment-ready image, no __syncthreads in the main loop.
#define SS_STR  76
#define SS_WBUF (16 * SS_STR)              // 1216 floats per buffer
#define SMEM_MAIN (8 * 2 * SS_WBUF * 4)    // 77824 B

__global__ void __launch_bounds__(256, 2) k_main(const float* __restrict__ bias,
                                                 float* __restrict__ out) {
    extern __shared__ __align__(16) float dyn[];

    int h = blockIdx.x;
    int b = blockIdx.y;
    int tid  = threadIdx.x;
    int warp = tid >> 5;
    int lane = tid & 31;
    int g  = lane >> 2;      // mma group (n-col / a-row)
    int tg = lane & 3;       // thread-in-group (k-row)
    int hw = lane >> 4;      // gather: pixel of pair
    int f4 = lane & 15;      // gather: float4 chunk of 64 channels

    int px0 = warp * 16;
    float* ssw = dyn + warp * 2 * SS_WBUF;

    size_t rowbase = (size_t)(b * HH + h) * WW;
    const float* offbase = &g_off[(rowbase + px0 + hw) * 18];   // step 2 px = 36 floats
    const float* xTb = &g_xT[(size_t)b * HH * WW * CC];

    float d[8][4];
#pragma unroll
    for (int j = 0; j < 8; j++)
#pragma unroll
        for (int i = 0; i < 4; i++) d[j][i] = 0.f;

    // ---- prologue: gather tap 0 into buffer 0 ----
    {
        int ky = -1, kx = -1;          // tap 0 deltas
        float offy[8], offx[8];
#pragma unroll
        for (int p = 0; p < 8; p++) {
            offy[p] = offbase[p * 36];
            offx[p] = offbase[p * 36 + 9];
        }
#pragma unroll
        for (int p = 0; p < 8; p++) {
            int pl  = p * 2 + hw;
            int pix = px0 + pl;
            float sy = (float)(h + ky) + offy[p];
            float sx = (float)(pix + kx) + offx[p];
            float fy0 = floorf(sy), fx0 = floorf(sx);
            int iy0 = (int)fy0, ix0 = (int)fx0;
            float ay = sy - fy0, ax = sx - fx0;
            float wy[2] = {1.f - ay, ay};
            float wx[2] = {1.f - ax, ax};
            float v0 = 0.f, v1 = 0.f, v2 = 0.f, v3 = 0.f;
#pragma unroll
            for (int q = 0; q < 4; q++) {
                int iy = iy0 + (q >> 1), ix = ix0 + (q & 1);
                bool ok = (iy >= 0 && iy < HH && ix >= 0 && ix < WW);
                float wt = ok ? wy[q >> 1] * wx[q & 1] : 0.f;
                int iyc = min(max(iy, 0), HH - 1);
                int ixc = min(max(ix, 0), WW - 1);
                float4 a = reinterpret_cast<const float4*>(
                    &xTb[((size_t)iyc * WW + ixc) * CC])[f4];
                v0 = fmaf(wt, a.x, v0);
                v1 = fmaf(wt, a.y, v1);
                v2 = fmaf(wt, a.z, v2);
                v3 = fmaf(wt, a.w, v3);
            }
            *reinterpret_cast<float4*>(&ssw[pl * SS_STR + f4 * 4]) =
                make_float4(v0, v1, v2, v3);
        }
    }
    __syncwarp();

    // ---- main loop: MMA(tap k) interleaved with gather(tap k+1) ----
#pragma unroll 1
    for (int k = 0; k < K2; k++) {
        int cur = k & 1;
        float* scur = ssw + cur * SS_WBUF;
        float* salt = ssw + (cur ^ 1) * SS_WBUF;
        bool have = (k < K2 - 1);

        int kn = k + 1;
        int ky = kn / 3 - 1, kx = kn % 3 - 1;
        float offy[8], offx[8];
        if (have) {
#pragma unroll
            for (int p = 0; p < 8; p++) {
                offy[p] = offbase[p * 36 + kn];
                offx[p] = offbase[p * 36 + 9 + kn];
            }
        }

        const float4* wfp = &g_wf[(size_t)(k * 64) * 32 + lane];

#pragma unroll
        for (int p = 0; p < 8; p++) {
            // --- issue gather corner LDGs for tap k+1 (consumed after MMA) ---
            float4 cv[4];
            float cw[4];
            int pl  = p * 2 + hw;
            int pix = px0 + pl;
            if (have) {
                float sy = (float)(h + ky) + offy[p];
                float sx = (float)(pix + kx) + offx[p];
                float fy0 = floorf(sy), fx0 = floorf(sx);
                int iy0 = (int)fy0, ix0 = (int)fx0;
                float ay = sy - fy0, ax = sx - fx0;
                float wy[2] = {1.f - ay, ay};
                float wx[2] = {1.f - ax, ax};
#pragma unroll
                for (int q = 0; q < 4; q++) {
                    int iy = iy0 + (q >> 1), ix = ix0 + (q & 1);
                    bool ok = (iy >= 0 && iy < HH && ix >= 0 && ix < WW);
                    cw[q] = ok ? wy[q >> 1] * wx[q & 1] : 0.f;
                    int iyc = min(max(iy, 0), HH - 1);
                    int ixc = min(max(ix, 0), WW - 1);
                    cv[q] = reinterpret_cast<const float4*>(
                        &xTb[((size_t)iyc * WW + ixc) * CC])[f4];
                }
            }

            // --- MMA k-step s = p ---
            {
                int kk = p * 8 + tg;
                float v0 = scur[g * SS_STR + kk];
                float v1 = scur[(g + 8) * SS_STR + kk];
                float v2 = scur[g * SS_STR + kk + 4];
                float v3 = scur[(g + 8) * SS_STR + kk + 4];
                uint32_t ah[4], al[4];
                ah[0] = tf32_bits(v0); al[0] = tf32_bits(v0 - __uint_as_float(ah[0]));
                ah[1] = tf32_bits(v1); al[1] = tf32_bits(v1 - __uint_as_float(ah[1]));
                ah[2] = tf32_bits(v2); al[2] = tf32_bits(v2 - __uint_as_float(ah[2]));
                ah[3] = tf32_bits(v3); al[3] = tf32_bits(v3 - __uint_as_float(ah[3]));

                const float4* wfs = wfp + (size_t)p * 8 * 32;
#pragma unroll
                for (int j = 0; j < 8; j++) {
                    float4 bf = wfs[j * 32];
                    mma_tf32(d[j], ah, bf.x, bf.y);
                    mma_tf32(d[j], al, bf.x, bf.y);
                    mma_tf32(d[j], ah, bf.z, bf.w);
                }
            }

            // --- combine + STS to alternate buffer ---
            if (have) {
                float v0 = 0.f, v1 = 0.f, v2 = 0.f, v3 = 0.f;
#pragma unroll
                for (int q = 0; q < 4; q++) {
                    v0 = fmaf(cw[q], cv[q].x, v0);
                    v1 = fmaf(cw[q], cv[q].y, v1);
                    v2 = fmaf(cw[q], cv[q].z, v2);
                    v3 = fmaf(cw[q], cv[q].w, v3);
                }
                *reinterpret_cast<float4*>(&salt[pl * SS_STR + f4 * 4]) =
                    make_float4(v0, v1, v2, v3);
            }
        }
        __syncwarp();
    }

    // ---- epilogue: mod/bias, per-warp smem transpose, float4 NCHW stores ----
    {
        float* ob = ssw;               // reuse buffer 0: [64 o][16 px]
        float mm0 = g_mm[rowbase + px0 + g];
        float mm1 = g_mm[rowbase + px0 + g + 8];
#pragma unroll
        for (int j = 0; j < 8; j++) {
            int o = j * 8 + 2 * tg;
            float b0 = bias[o], b1 = bias[o + 1];
            ob[o * 16 + g]            = d[j][0] * mm0 + b0;
            ob[(o + 1) * 16 + g]      = d[j][1] * mm0 + b1;
            ob[o * 16 + g + 8]        = d[j][2] * mm1 + b0;
            ob[(o + 1) * 16 + g + 8]  = d[j][3] * mm1 + b1;
        }
        __syncwarp();
#pragma unroll
        for (int p = 0; p < 8; p++) {
            int fidx = p * 32 + lane;
            int o = fidx >> 2;
            int q = fidx & 3;
            float4 v = *reinterpret_cast<const float4*>(&ob[o * 16 + q * 4]);
            *reinterpret_cast<float4*>(
                &out[((size_t)(b * OO + o) * HH + h) * WW + px0 + q * 4]) = v;
        }
    }
}

// ---------------- launch -----------------------------------------------------
extern "C" void kernel_launch(void* const* d_in, const int* in_sizes, int n_in,
                              void* d_out, int out_size) {
    const float* x        = (const float*)d_in[0];
    const float* weight   = (const float*)d_in[1];
    const float* bias     = (const float*)d_in[2];
    const float* offset_w = (const float*)d_in[3];
    const float* offset_b = (const float*)d_in[4];
    const float* mod_w    = (const float*)d_in[5];
    const float* mod_b    = (const float*)d_in[6];
    float* out = (float*)d_out;

    cudaFuncSetAttribute(k_main, cudaFuncAttributeMaxDynamicSharedMemorySize,
                         SMEM_MAIN);
    cudaFuncSetAttribute(k_offmod, cudaFuncAttributeMaxDynamicSharedMemorySize,
                         SMEM_OFFMOD);

    k_transpose<<<BB * HH, 256>>>(x);
    k_wreorg<<<72, 256>>>(weight);
    k_offmod<<<dim3(HH / 2, BB), 256, SMEM_OFFMOD>>>(offset_w, offset_b,
                                                     mod_w, mod_b);
    k_main<<<dim3(HH, BB), 256, SMEM_MAIN>>>(bias, out);
}